// round 15
// baseline (speedup 1.0000x reference)
#include <cuda_runtime.h>
#include <cuda_bf16.h>
#include <cstdint>

// Problem constants
#define BATCH   4
#define SEQL    8192
#define DIM     1024
#define HEADS   8
#define SPAN    16                      // rows per block
#define GROW    4                       // rows per register group
#define NGROUP  (SPAN / GROW)           // 4
#define NSPAN   (SEQL / SPAN)           // 512
#define NBLK    (BATCH * NSPAN)         // 2048
#define THREADS 256
#define NWARP   (THREADS / 32)          // 8
#define LN_EPS  1e-5f

// Scratch
__device__ float g_yend[(size_t)NBLK * DIM];       // partial: local end state
__device__ float g_sinc[(size_t)NBLK * DIM];       // inclusive: true EMA end state
__device__ int   g_sync[NBLK * NWARP + 1];         // per-warp counters + ticket (last)
                                                   // >=32: partial ready, >=64: inclusive ready

__device__ __forceinline__ int ld_acquire(const int* p) {
    int v;
    asm volatile("ld.global.acquire.gpu.b32 %0, [%1];" : "=r"(v) : "l"(p));
    return v;
}
__device__ __forceinline__ void red_release_add(int* p) {
    asm volatile("red.release.gpu.global.add.s32 [%0], 1;" :: "l"(p) : "memory");
}

extern "C" __global__ void __launch_bounds__(THREADS, 3)
mhesa_fused(const float* __restrict__ x,
            const float* __restrict__ gamma,
            const float* __restrict__ beta,
            const float* __restrict__ alphas,
            const float* __restrict__ paramD,
            float* __restrict__ out)
{
    extern __shared__ float4 s_r[];                // [SPAN][DIM/4] local results, 64 KB
    __shared__ float  s_s [GROW][THREADS];         // per-row partial sums
    __shared__ float  s_ss[GROW][THREADS];         // per-row partial sumsq
    __shared__ float2 s_stat[GROW];                // (mean, rstd) current group
    __shared__ int    s_ticket;

    const int tid  = threadIdx.x;
    const int lane = tid & 31;
    const int w    = tid >> 5;

    // Ticket: scheduling-order (b,c) assignment -> lookback predecessors resident.
    if (tid == 0) s_ticket = atomicAdd(&g_sync[NBLK * NWARP], 1);
    __syncthreads();
    const int t = s_ticket;
    const int b = t & (BATCH - 1);
    const int c = t >> 2;                          // span index 0..NSPAN-1

    const size_t base = ((size_t)b * SEQL + (size_t)c * SPAN) * DIM;
    const float4* __restrict__ xc = (const float4*)(x + base);
    float4* __restrict__ oc = (float4*)(out + base);

    const float4 gm = ((const float4*)gamma )[tid];
    const float4 bt = ((const float4*)beta  )[tid];
    const float4 pd = ((const float4*)paramD)[tid];
    const float  alp = alphas[w];                  // head = tid>>5, warp-uniform
    const float  a   = 1.f / (1.f + expf(-alp));
    const float  dec = 1.f - a;

    // Double-buffered register tile: 2 x 4 rows x float4 per thread.
    float4 buf[2][GROW];

    // Prologue: issue loads for group 0.
    #pragma unroll
    for (int j = 0; j < GROW; j++)
        buf[0][j] = xc[j * (DIM / 4) + tid];

    float4 y = make_float4(0.f, 0.f, 0.f, 0.f);

    // -------- Stream phase: x -> LN -> EMA -> r into smem --------------------
    #pragma unroll
    for (int g = 0; g < NGROUP; g++) {
        const int bi = g & 1;
        if (g + 1 < NGROUP) {
            #pragma unroll
            for (int j = 0; j < GROW; j++)
                buf[bi ^ 1][j] = xc[((g + 1) * GROW + j) * (DIM / 4) + tid];
        }

        #pragma unroll
        for (int j = 0; j < GROW; j++) {
            float4 v = buf[bi][j];
            s_s [j][tid] = (v.x + v.y) + (v.z + v.w);
            s_ss[j][tid] = v.x * v.x + v.y * v.y + v.z * v.z + v.w * v.w;
        }
        __syncthreads();                           // partials ready

        if (w < GROW) {
            float s = 0.f, ss = 0.f;
            #pragma unroll
            for (int k = 0; k < THREADS / 32; k++) {
                s  += s_s [w][lane + 32 * k];
                ss += s_ss[w][lane + 32 * k];
            }
            #pragma unroll
            for (int o = 16; o; o >>= 1) {
                s  += __shfl_xor_sync(0xffffffffu, s,  o);
                ss += __shfl_xor_sync(0xffffffffu, ss, o);
            }
            if (lane == 0) {
                float m   = s * (1.f / DIM);
                float var = ss * (1.f / DIM) - m * m;
                s_stat[w] = make_float2(m, rsqrtf(var + LN_EPS));
            }
        }
        __syncthreads();                           // stats ready

        #pragma unroll
        for (int j = 0; j < GROW; j++) {
            float4 v = buf[bi][j];
            const float m  = s_stat[j].x;
            const float rs = s_stat[j].y;
            float4 u;
            u.x = (v.x - m) * rs * gm.x + bt.x;
            u.y = (v.y - m) * rs * gm.y + bt.y;
            u.z = (v.z - m) * rs * gm.z + bt.z;
            u.w = (v.w - m) * rs * gm.w + bt.w;
            y.x = fmaf(dec, y.x, a * u.x);
            y.y = fmaf(dec, y.y, a * u.y);
            y.z = fmaf(dec, y.z, a * u.z);
            y.w = fmaf(dec, y.w, a * u.w);
            float4 r;
            r.x = fmaf(u.x, pd.x, y.x);
            r.y = fmaf(u.y, pd.y, y.y);
            r.z = fmaf(u.z, pd.z, y.z);
            r.w = fmaf(u.w, pd.w, y.w);
            s_r[(g * GROW + j) * (DIM / 4) + tid] = r;
        }
    }

    const int span_id = b * NSPAN + c;
    int* const my_flag = &g_sync[span_id * NWARP + w];

    // -------- Publish PARTIAL: yend store + release (counter -> 32) ---------
    {
        float4* ye = (float4*)g_yend + (size_t)span_id * (DIM / 4);
        ye[tid] = y;
        red_release_add(my_flag);
    }

    float dch = dec;                               // dec^SPAN via 4 squarings
    #pragma unroll
    for (int i = 0; i < 4; i++) dch *= dch;

    // -------- Lookback: walk partials until an INCLUSIVE predecessor --------
    float4 carry = make_float4(0.f, 0.f, 0.f, 0.f);
    if (c > 0) {
        float f = 1.f;
        int p = c - 1;
        const float4* yeb = (const float4*)g_yend + (size_t)b * NSPAN * (DIM / 4);
        const float4* seb = (const float4*)g_sinc + (size_t)b * NSPAN * (DIM / 4);
        for (;;) {
            const int* flag = &g_sync[(b * NSPAN + p) * NWARP + w];
            int v;
            do { v = ld_acquire(flag); } while (v < 32);
            const bool inc = __all_sync(0xffffffffu, v >= 64);  // uniform + safe
            if (inc) {
                float4 s = __ldcg(seb + (size_t)p * (DIM / 4) + tid);
                carry.x = fmaf(f, s.x, carry.x);
                carry.y = fmaf(f, s.y, carry.y);
                carry.z = fmaf(f, s.z, carry.z);
                carry.w = fmaf(f, s.w, carry.w);
                break;                             // inclusive = full prefix; stop
            }
            float4 yv = __ldcg(yeb + (size_t)p * (DIM / 4) + tid);
            carry.x = fmaf(f, yv.x, carry.x);
            carry.y = fmaf(f, yv.y, carry.y);
            carry.z = fmaf(f, yv.z, carry.z);
            carry.w = fmaf(f, yv.w, carry.w);
            f *= dch;
            p--;
            if (p < 0 || f <= 1e-5f) break;        // decay cap (warp-uniform)
        }
    }

    // -------- Publish INCLUSIVE: S_c = yend + dec^SPAN * carry (-> 64) ------
    {
        float4* si = (float4*)g_sinc + (size_t)span_id * (DIM / 4);
        float4 S;
        S.x = fmaf(dch, carry.x, y.x);
        S.y = fmaf(dch, carry.y, y.y);
        S.z = fmaf(dch, carry.z, y.z);
        S.w = fmaf(dch, carry.w, y.w);
        si[tid] = S;
        red_release_add(my_flag);
    }

    // -------- Merged store: out = r_smem + carry * dec^(l+1) ----------------
    #pragma unroll
    for (int l = 0; l < SPAN; l++) {
        const float pw = dec * __powf(dec, (float)l);   // dec^(l+1)
        float4 v = s_r[l * (DIM / 4) + tid];
        v.x = fmaf(carry.x, pw, v.x);
        v.y = fmaf(carry.y, pw, v.y);
        v.z = fmaf(carry.z, pw, v.z);
        v.w = fmaf(carry.w, pw, v.w);
        oc[l * (DIM / 4) + tid] = v;
    }
}

extern "C" void kernel_launch(void* const* d_in, const int* in_sizes, int n_in,
                              void* d_out, int out_size)
{
    const float* x      = (const float*)d_in[0];
    const float* gamma  = (const float*)d_in[1];
    const float* beta   = (const float*)d_in[2];
    const float* alphas = (const float*)d_in[3];
    const float* paramD = (const float*)d_in[4];
    float* out = (float*)d_out;

    // Reset flags + ticket (capture-legal stream memset).
    void* sym = nullptr;
    cudaGetSymbolAddress(&sym, g_sync);
    cudaMemsetAsync(sym, 0, sizeof(int) * (NBLK * NWARP + 1), 0);

    static bool attr_done = false;
    const int smem_bytes = SPAN * DIM * sizeof(float);   // 65536
    if (!attr_done) {
        cudaFuncSetAttribute(mhesa_fused,
                             cudaFuncAttributeMaxDynamicSharedMemorySize, smem_bytes);
        attr_done = true;
    }

    mhesa_fused<<<NBLK, THREADS, smem_bytes>>>(x, gamma, beta, alphas, paramD, out);
}